// round 16
// baseline (speedup 1.0000x reference)
#include <cuda_runtime.h>
#include <cuda_fp16.h>
#include <math.h>
#include <stdint.h>

// ---------------- problem constants ----------------
#define BN_  8192   // batch (GEMM M)
#define TN_  658    // seq len / final out features
#define TP_  672    // K-pad for layer1 (21 * 32)
#define IN_  7
#define D1_  1024
#define D2_  512
#define D3_  128
#define N4P_ 768    // w4 N padded (658 -> 768)

// ---------------- scratch ----------------
__device__ __half g_hsT[(size_t)TP_ * BN_];   // [t][b] fp16, K-padded (A^T of GEMM1)
__device__ __half g_c1 [(size_t)BN_ * D1_];
__device__ __half g_c2 [(size_t)BN_ * D2_];
__device__ __half g_c3 [(size_t)BN_ * D3_];
__device__ __half g_w1c[D1_ * TP_];
__device__ __half g_w2c[D2_ * D1_];
__device__ __half g_w3c[D3_ * D2_];
__device__ __half g_w4c[N4P_ * D3_];

// ---------------- helpers ----------------
__device__ __forceinline__ uint32_t smem_u32(const void* p) {
    uint32_t a;
    asm("{ .reg .u64 t; cvta.to.shared.u64 t, %1; cvt.u32.u64 %0, t; }" : "=r"(a) : "l"(p));
    return a;
}
#define CP16(sa, ga) asm volatile("cp.async.cg.shared.global [%0], [%1], 16;" :: "r"(sa), "l"(ga))
#define CP8(sa, ga)  asm volatile("cp.async.ca.shared.global [%0], [%1], 8;"  :: "r"(sa), "l"(ga))
#define CP_COMMIT()  asm volatile("cp.async.commit_group;" ::: "memory")
#define CP_WAIT1()   asm volatile("cp.async.wait_group 1;" ::: "memory")
#define CP_WAIT2()   asm volatile("cp.async.wait_group 2;" ::: "memory")

#define LDSM4(r0, r1, r2, r3, a)                                                 \
    asm volatile("ldmatrix.sync.aligned.m8n8.x4.shared.b16 {%0,%1,%2,%3}, [%4];" \
        : "=r"(r0), "=r"(r1), "=r"(r2), "=r"(r3) : "r"(a))
#define LDSM4T(r0, r1, r2, r3, a)                                                      \
    asm volatile("ldmatrix.sync.aligned.m8n8.x4.trans.shared.b16 {%0,%1,%2,%3}, [%4];" \
        : "=r"(r0), "=r"(r1), "=r"(r2), "=r"(r3) : "r"(a))

__device__ __forceinline__ void mma_f16(float* d, const uint32_t* a, const uint32_t* b) {
    asm volatile(
        "mma.sync.aligned.m16n8k16.row.col.f32.f16.f16.f32 "
        "{%0,%1,%2,%3}, {%4,%5,%6,%7}, {%8,%9}, {%0,%1,%2,%3};"
        : "+f"(d[0]), "+f"(d[1]), "+f"(d[2]), "+f"(d[3])
        : "r"(a[0]), "r"(a[1]), "r"(a[2]), "r"(a[3]), "r"(b[0]), "r"(b[1]));
}

// ---------------- fused weight prep (pad + fp16 convert) ----------------
#define WSEG1 (D1_ * TP_)
#define WSEG2 (D2_ * D1_)
#define WSEG3 (D3_ * D2_)
#define WSEG4 (N4P_ * D3_)
#define WTOT  (WSEG1 + WSEG2 + WSEG3 + WSEG4)

__global__ void wprep_all(const float* __restrict__ w1, const float* __restrict__ w2,
                          const float* __restrict__ w3, const float* __restrict__ w4,
                          __half* __restrict__ w1c, __half* __restrict__ w2c,
                          __half* __restrict__ w3c, __half* __restrict__ w4c)
{
    int idx = blockIdx.x * blockDim.x + threadIdx.x;
    if (idx < WSEG1) {
        int n = idx / TP_, k = idx - n * TP_;
        w1c[idx] = (k < TN_) ? __float2half_rn(w1[n * TN_ + k]) : __float2half_rn(0.0f);
        return;
    }
    idx -= WSEG1;
    if (idx < WSEG2) { w2c[idx] = __float2half_rn(w2[idx]); return; }
    idx -= WSEG2;
    if (idx < WSEG3) { w3c[idx] = __float2half_rn(w3[idx]); return; }
    idx -= WSEG3;
    if (idx < WSEG4) {
        int n = idx / D3_, k = idx - n * D3_;
        w4c[idx] = (n < TN_) ? __float2half_rn(w4[n * D3_ + k]) : __float2half_rn(0.0f);
    }
}

// ---------------- FUSED input projection + recurrence ----------------
// 128 CTAs x 64 b, 128 threads. cp.async ring of 4 stages, each 64 rows x
// (16 t x 7) floats, row stride 118 (8B aligned, <=2-way LDS conflicts).
// Threads 0..63 run the recurrence, computing xw inline from smem (off the
// h-chain -> hidden under tanh latency). All 128 threads issue loads.
#define F_TT    16
#define F_NT    42                  // ceil(658/16) tiles; 42*16 = 672 = TP_
#define F_ROW   118                 // floats per b-row per tile
#define F_STAGE (64 * F_ROW)        // floats
#define F_SMEM  (4 * F_STAGE * 4)   // 120832 B

__global__ __launch_bounds__(128)
void fused_rnn(const float* __restrict__ x,
               const float* __restrict__ h0,
               const float* __restrict__ Wih,
               const float* __restrict__ Whh,
               const float* __restrict__ bih,
               const float* __restrict__ bhh,
               __half* __restrict__ hsT,
               float* __restrict__ hidden)
{
    extern __shared__ float ring[];
    int tid = threadIdx.x;
    int b0 = blockIdx.x * 64;

    float w0 = Wih[0], w1 = Wih[1], w2 = Wih[2], w3 = Wih[3];
    float w4 = Wih[4], w5 = Wih[5], w6 = Wih[6];
    float a = Whh[0];
    float bias = bih[0] + bhh[0];

    float h = 0.0f;
    if (tid < 64) h = h0[b0 + tid];

    auto load_tile = [&](int tt) {
        int t0 = tt * F_TT;
        int nt = (TN_ - t0 < F_TT) ? (TN_ - t0) : F_TT;   // 16 or 2
        int nf2 = nt * IN_ / 2;                            // 56 or 7
        float* dst = ring + (tt & 3) * F_STAGE;
        int tot = 64 * nf2;
        for (int c = tid; c < tot; c += 128) {
            int r = c / nf2, o = c - r * nf2;
            CP8(smem_u32(dst + r * F_ROW + 2 * o),
                x + (size_t)(b0 + r) * (TN_ * IN_) + t0 * IN_ + 2 * o);
        }
        CP_COMMIT();
    };

    load_tile(0); load_tile(1); load_tile(2);

    for (int tt = 0; tt < F_NT; tt++) {
        if (tt + 3 < F_NT) load_tile(tt + 3);
        else               CP_COMMIT();
        CP_WAIT2();
        __syncthreads();

        if (tid < 64) {
            int t0 = tt * F_TT;
            const float* xr = ring + (tt & 3) * F_STAGE + tid * F_ROW;
            int jmax = (TN_ - t0 < F_TT) ? (TN_ - t0) : F_TT;
            if (jmax == F_TT) {
                #pragma unroll
                for (int j = 0; j < F_TT; j++) {
                    const float* p = xr + j * IN_;
                    float xw = bias;
                    xw = fmaf(p[0], w0, xw);
                    xw = fmaf(p[1], w1, xw);
                    xw = fmaf(p[2], w2, xw);
                    xw = fmaf(p[3], w3, xw);
                    xw = fmaf(p[4], w4, xw);
                    xw = fmaf(p[5], w5, xw);
                    xw = fmaf(p[6], w6, xw);
                    h = tanhf(fmaf(a, h, xw));
                    hsT[(size_t)(t0 + j) * BN_ + b0 + tid] = __float2half_rn(h);
                }
            } else {
                for (int j = 0; j < jmax; j++) {
                    const float* p = xr + j * IN_;
                    float xw = bias;
                    xw = fmaf(p[0], w0, xw);
                    xw = fmaf(p[1], w1, xw);
                    xw = fmaf(p[2], w2, xw);
                    xw = fmaf(p[3], w3, xw);
                    xw = fmaf(p[4], w4, xw);
                    xw = fmaf(p[5], w5, xw);
                    xw = fmaf(p[6], w6, xw);
                    h = tanhf(fmaf(a, h, xw));
                    hsT[(size_t)(t0 + j) * BN_ + b0 + tid] = __float2half_rn(h);
                }
            }
        }
        __syncthreads();
    }

    if (tid < 64) {
        #pragma unroll
        for (int t = TN_; t < TP_; t++)
            hsT[(size_t)t * BN_ + b0 + tid] = __float2half_rn(0.0f);
        if (hidden) hidden[b0 + tid] = h;
    }
}

// ---------------- fp16 mma GEMM (m16n8k16, fp32 accum, 3-stage) — round-11 best ----------------
template<int MT, bool ATRANS, bool RELU, bool GUARDN, bool OUTF32>
__global__ __launch_bounds__(256, 2)
void gemm_h(const __half* __restrict__ A, int lda,
            const __half* __restrict__ Bw, int ldb,
            const float* __restrict__ bias,
            void* __restrict__ Cv, int ldc, int Nreal, int K)
{
    constexpr int BM = MT * 32;
    constexpr int A_STAGE = ATRANS ? 32 * 136 : BM * 40;   // halves
    constexpr int B_STAGE = 128 * 40;

    extern __shared__ __half smh[];
    __half* As = smh;
    __half* Bs = smh + 3 * A_STAGE;

    int tid = threadIdx.x;
    int lane = tid & 31;
    int wid  = tid >> 5;
    int wm = wid & 1;
    int wn = wid >> 1;
    int grp = lane >> 2;
    int qk  = lane & 3;
    int m0 = blockIdx.y * BM;
    int n0 = blockIdx.x * 128;

    uint32_t aBase;
    if (ATRANS) {
        int kRow = (lane & 7) + ((lane >> 4) & 1) * 8;
        int mCol = wm * (MT * 16) + ((lane >> 3) & 1) * 8;
        aBase = smem_u32(As) + (uint32_t)(kRow * 136 + mCol) * 2;
    } else {
        int aRow = wm * (MT * 16) + (lane & 7) + ((lane >> 3) & 1) * 8;
        int aCol = ((lane >> 4) & 1) * 8;
        aBase = smem_u32(As) + (uint32_t)(aRow * 40 + aCol) * 2;
    }
    int bRow = wn * 32 + (lane & 7) + ((lane >> 4) & 1) * 8;
    int bCol = ((lane >> 3) & 1) * 8;
    uint32_t bBase = smem_u32(Bs) + (uint32_t)(bRow * 40 + bCol) * 2;

    float acc[MT][4][4];
    #pragma unroll
    for (int i = 0; i < MT; i++)
        #pragma unroll
        for (int j = 0; j < 4; j++)
            #pragma unroll
            for (int q = 0; q < 4; q++) acc[i][j][q] = 0.0f;

    const int KT = K >> 5;

    auto load_stage = [&](int kt, int s) {
        __half* aS = As + s * A_STAGE;
        __half* bS = Bs + s * B_STAGE;
        if (ATRANS) {
            const __half* Ap = A + (size_t)(kt * 32) * lda + m0;
            #pragma unroll
            for (int i = 0; i < 2; i++) {
                int c = i * 256 + tid;
                int r = c >> 4, co = (c & 15) << 3;
                CP16(smem_u32(aS + r * 136 + co), Ap + (size_t)r * lda + co);
            }
        } else {
            const __half* Ap = A + (size_t)m0 * lda + kt * 32;
            #pragma unroll
            for (int i = 0; i < BM / 64; i++) {
                int c = i * 256 + tid;
                int r = c >> 2, co = (c & 3) << 3;
                CP16(smem_u32(aS + r * 40 + co), Ap + (size_t)r * lda + co);
            }
        }
        const __half* Bp = Bw + (size_t)n0 * ldb + kt * 32;
        #pragma unroll
        for (int i = 0; i < 2; i++) {
            int c = i * 256 + tid;
            int r = c >> 2, co = (c & 3) << 3;
            CP16(smem_u32(bS + r * 40 + co), Bp + (size_t)r * ldb + co);
        }
        CP_COMMIT();
    };

    load_stage(0, 0);
    if (KT > 1) load_stage(1, 1); else CP_COMMIT();

    for (int kt = 0; kt < KT; kt++) {
        int s = kt % 3;
        if (kt + 2 < KT) load_stage(kt + 2, (kt + 2) % 3);
        else             CP_COMMIT();
        CP_WAIT2();
        __syncthreads();

        uint32_t aSt = aBase + (uint32_t)(s * A_STAGE) * 2;
        uint32_t bSt = bBase + (uint32_t)(s * B_STAGE) * 2;

        #pragma unroll
        for (int ks = 0; ks < 2; ks++) {
            uint32_t af[MT][4], bf[4][2];
            if (ATRANS) {
                uint32_t aAddr = aSt + (uint32_t)(ks * 16 * 136) * 2;
                #pragma unroll
                for (int mt = 0; mt < MT; mt++)
                    LDSM4T(af[mt][0], af[mt][1], af[mt][2], af[mt][3],
                           aAddr + (uint32_t)(mt * 16) * 2);
            } else {
                uint32_t aAddr = aSt + ks * 32;
                #pragma unroll
                for (int mt = 0; mt < MT; mt++)
                    LDSM4(af[mt][0], af[mt][1], af[mt][2], af[mt][3],
                          aAddr + (uint32_t)(mt * 16 * 40) * 2);
            }
            uint32_t bAddr = bSt + ks * 32;
            #pragma unroll
            for (int ntp = 0; ntp < 2; ntp++)
                LDSM4(bf[2 * ntp][0], bf[2 * ntp][1], bf[2 * ntp + 1][0], bf[2 * ntp + 1][1],
                      bAddr + (uint32_t)(ntp * 16 * 40) * 2);
            #pragma unroll
            for (int mt = 0; mt < MT; mt++)
                #pragma unroll
                for (int nt = 0; nt < 4; nt++)
                    mma_f16(acc[mt][nt], af[mt], bf[nt]);
        }
        __syncthreads();
    }

    // ---- epilogue ----
    #pragma unroll
    for (int mt = 0; mt < MT; mt++) {
        int r0 = m0 + wm * (MT * 16) + mt * 16 + grp;
        #pragma unroll
        for (int nt = 0; nt < 4; nt++) {
            int nc = n0 + wn * 32 + nt * 8 + 2 * qk;
            if (GUARDN && nc >= Nreal) continue;
            float b0v = bias[nc], b1v = bias[nc + 1];
            float v00 = acc[mt][nt][0] + b0v, v01 = acc[mt][nt][1] + b1v;
            float v10 = acc[mt][nt][2] + b0v, v11 = acc[mt][nt][3] + b1v;
            if (RELU) {
                v00 = fmaxf(v00, 0.0f); v01 = fmaxf(v01, 0.0f);
                v10 = fmaxf(v10, 0.0f); v11 = fmaxf(v11, 0.0f);
            }
            if (OUTF32) {
                float* C = (float*)Cv;
                *(float2*)(C + (size_t)r0 * ldc + nc)       = make_float2(v00, v01);
                *(float2*)(C + (size_t)(r0 + 8) * ldc + nc) = make_float2(v10, v11);
            } else {
                __half* C = (__half*)Cv;
                *(__half2*)(C + (size_t)r0 * ldc + nc)       = __floats2half2_rn(v00, v01);
                *(__half2*)(C + (size_t)(r0 + 8) * ldc + nc) = __floats2half2_rn(v10, v11);
            }
        }
    }
}

// ---------------- launcher ----------------
#define SMEM_G1  (3 * (32 * 136 + 128 * 40) * 2)
#define SMEM_MT4 (3 * (128 * 40 + 128 * 40) * 2)
#define SMEM_MT2 (3 * (64 * 40 + 128 * 40) * 2)

extern "C" void kernel_launch(void* const* d_in, const int* in_sizes, int n_in,
                              void* d_out, int out_size)
{
    const float* x   = (const float*)d_in[0];
    const float* h0  = (const float*)d_in[1];
    const float* Wih = (const float*)d_in[2];
    const float* Whh = (const float*)d_in[3];
    const float* bih = (const float*)d_in[4];
    const float* bhh = (const float*)d_in[5];
    const float* w1  = (const float*)d_in[6];
    const float* b1  = (const float*)d_in[7];
    const float* w2  = (const float*)d_in[8];
    const float* b2  = (const float*)d_in[9];
    const float* w3  = (const float*)d_in[10];
    const float* b3  = (const float*)d_in[11];
    const float* w4  = (const float*)d_in[12];
    const float* b4  = (const float*)d_in[13];
    float* out = (float*)d_out;

    __half *hsT, *c1, *c2, *c3, *w1c, *w2c, *w3c, *w4c;
    cudaGetSymbolAddress((void**)&hsT, g_hsT);
    cudaGetSymbolAddress((void**)&c1,  g_c1);
    cudaGetSymbolAddress((void**)&c2,  g_c2);
    cudaGetSymbolAddress((void**)&c3,  g_c3);
    cudaGetSymbolAddress((void**)&w1c, g_w1c);
    cudaGetSymbolAddress((void**)&w2c, g_w2c);
    cudaGetSymbolAddress((void**)&w3c, g_w3c);
    cudaGetSymbolAddress((void**)&w4c, g_w4c);

    cudaFuncSetAttribute(fused_rnn, cudaFuncAttributeMaxDynamicSharedMemorySize, F_SMEM);
    cudaFuncSetAttribute(gemm_h<4, true,  true,  false, false>, cudaFuncAttributeMaxDynamicSharedMemorySize, SMEM_G1);
    cudaFuncSetAttribute(gemm_h<4, false, true,  false, false>, cudaFuncAttributeMaxDynamicSharedMemorySize, SMEM_MT4);
    cudaFuncSetAttribute(gemm_h<2, false, true,  false, false>, cudaFuncAttributeMaxDynamicSharedMemorySize, SMEM_MT2);
    cudaFuncSetAttribute(gemm_h<4, false, false, true,  true >, cudaFuncAttributeMaxDynamicSharedMemorySize, SMEM_MT4);

    // weight prep
    wprep_all<<<(WTOT + 255) / 256, 256>>>(w1, w2, w3, w4, w1c, w2c, w3c, w4c);

    // fused input projection + recurrence -> hsT fp16 [t][b]
    float* hidden = (out_size >= BN_ * TN_ + BN_) ? (out + (size_t)BN_ * TN_) : nullptr;
    fused_rnn<<<BN_ / 64, 128, F_SMEM>>>(x, h0, Wih, Whh, bih, bhh, hsT, hidden);

    // GEMM chain on fp16 mma (round-11 best config)
    gemm_h<4, true,  true,  false, false><<<dim3(D1_ / 128, BN_ / 128), 256, SMEM_G1 >>>(hsT, BN_, w1c, TP_, b1, c1,  D1_, D1_, TP_);
    gemm_h<4, false, true,  false, false><<<dim3(D2_ / 128, BN_ / 128), 256, SMEM_MT4>>>(c1,  D1_, w2c, D1_, b2, c2,  D2_, D2_, D1_);
    gemm_h<2, false, true,  false, false><<<dim3(D3_ / 128, BN_ / 64 ), 256, SMEM_MT2>>>(c2,  D2_, w3c, D2_, b3, c3,  D3_, D3_, D2_);
    gemm_h<4, false, false, true,  true ><<<dim3(N4P_ / 128, BN_ / 128), 256, SMEM_MT4>>>(c3,  D3_, w4c, D3_, b4, out, TN_, TN_, D3_);
}